// round 2
// baseline (speedup 1.0000x reference)
#include <cuda_runtime.h>
#include <math.h>

#define NJ   400000
#define F    128
#define NBLK 1184
#define TPB  256
#define WPB  (TPB / 32)

// Scratch (allocation-free rule: __device__ globals)
__device__ float g_v[F];
__device__ float g_c0;
__device__ float g_m[NBLK];
__device__ float g_s[NBLK];
__device__ float g_u[NBLK * F];

// ---------------------------------------------------------------------------
// Kernel A: tiny precompute.
//   z_i[f] = W_i_w[f,:]·h_i + W_i_b[f]
//   v[k]   = sum_f W_j_w[f,k] * w_r[f]          (w_r = W_ij[0,128:256])
//   c0     = sum_f w_l[f]*z_i[f] + W_j_b[f]*w_r[f]
// ---------------------------------------------------------------------------
__global__ void prep_kernel(const float* __restrict__ h_i,
                            const float* __restrict__ W_i_w,
                            const float* __restrict__ W_i_b,
                            const float* __restrict__ W_j_w,
                            const float* __restrict__ W_j_b,
                            const float* __restrict__ W_ij) {
    __shared__ float s_hi[F];
    __shared__ float sred[F];
    int t = threadIdx.x;  // 128 threads
    s_hi[t] = h_i[t];
    __syncthreads();

    float z = W_i_b[t];
#pragma unroll 4
    for (int k = 0; k < F; k++) z += W_i_w[t * F + k] * s_hi[k];

    // v[t]: column-t dot of W_j_w with w_r. Reads are coalesced across t.
    float v = 0.f;
    for (int f = 0; f < F; f++) v += W_j_w[f * F + t] * W_ij[F + f];
    g_v[t] = v;

    // c0 reduction
    sred[t] = W_ij[t] * z + W_j_b[t] * W_ij[F + t];
    __syncthreads();
    for (int off = 64; off > 0; off >>= 1) {
        if (t < off) sred[t] += sred[t + off];
        __syncthreads();
    }
    if (t == 0) g_c0 = sred[0];
}

// ---------------------------------------------------------------------------
// Kernel B: single streaming pass over h_j with online softmax.
// One warp per row; lane l owns h_j[row][4l:4l+4] as a float4.
// Per-warp state: running max m, running sum, 128-dim weighted accumulator
// (4 floats per lane). Block-combines 8 warps -> per-block partial in gmem.
// ---------------------------------------------------------------------------
__global__ void __launch_bounds__(TPB) pass_kernel(const float* __restrict__ h_j) {
    __shared__ float sv[F];
    __shared__ float red_m[WPB];
    __shared__ float red_s[WPB];
    __shared__ float red_u[WPB * F];
    __shared__ float s_mb;

    for (int i = threadIdx.x; i < F; i += TPB) sv[i] = g_v[i];
    __syncthreads();

    const float c0 = g_c0;
    const int warp = threadIdx.x >> 5;
    const int lane = threadIdx.x & 31;
    const int gw = blockIdx.x * WPB + warp;   // global warp id = first row
    const int nw = NBLK * WPB;                // total warps = row stride

    const float4 vv = reinterpret_cast<const float4*>(sv)[lane];
    const float4* __restrict__ hj4 = reinterpret_cast<const float4*>(h_j);

    float m = -1e30f, ssum = 0.f;
    float ux = 0.f, uy = 0.f, uz = 0.f, uw = 0.f;

    int row = gw;
    float4 x = make_float4(0.f, 0.f, 0.f, 0.f);
    if (row < NJ) x = __ldg(hj4 + (size_t)row * 32 + lane);

    while (row < NJ) {
        // Prefetch next row's data before the dependent chain (extra MLP).
        const int nrow = row + nw;
        float4 xn = x;
        if (nrow < NJ) xn = __ldg(hj4 + (size_t)nrow * 32 + lane);

        // s_j = c0 + h_j[row]·v  (warp-wide dot)
        float d = x.x * vv.x + x.y * vv.y + x.z * vv.z + x.w * vv.w;
        d += __shfl_xor_sync(0xffffffffu, d, 16);
        d += __shfl_xor_sync(0xffffffffu, d, 8);
        d += __shfl_xor_sync(0xffffffffu, d, 4);
        d += __shfl_xor_sync(0xffffffffu, d, 2);
        d += __shfl_xor_sync(0xffffffffu, d, 1);

        const float s = d + c0;
        const float e = (s > 0.f) ? s : 0.1f * s;     // leaky relu

        // Online softmax update
        const float mn    = fmaxf(m, e);
        const float scale = __expf(m - mn);
        const float w     = __expf(e - mn);
        ssum = ssum * scale + w;
        ux   = ux * scale + w * x.x;
        uy   = uy * scale + w * x.y;
        uz   = uz * scale + w * x.z;
        uw   = uw * scale + w * x.w;
        m = mn;

        x = xn;
        row = nrow;
    }

    if (lane == 0) { red_m[warp] = m; red_s[warp] = ssum; }
    red_u[warp * F + lane * 4 + 0] = ux;
    red_u[warp * F + lane * 4 + 1] = uy;
    red_u[warp * F + lane * 4 + 2] = uz;
    red_u[warp * F + lane * 4 + 3] = uw;
    __syncthreads();

    if (threadIdx.x == 0) {
        float mb = red_m[0];
        for (int w2 = 1; w2 < WPB; w2++) mb = fmaxf(mb, red_m[w2]);
        s_mb = mb;
    }
    __syncthreads();
    const float mb = s_mb;

    const int t = threadIdx.x;
    if (t < F) {
        float acc = 0.f;
#pragma unroll
        for (int w2 = 0; w2 < WPB; w2++)
            acc += __expf(red_m[w2] - mb) * red_u[w2 * F + t];
        g_u[blockIdx.x * F + t] = acc;
    }
    if (t == 0) {
        float sb = 0.f;
        for (int w2 = 0; w2 < WPB; w2++) sb += __expf(red_m[w2] - mb) * red_s[w2];
        g_s[blockIdx.x] = sb;
        g_m[blockIdx.x] = mb;
    }
}

// ---------------------------------------------------------------------------
// Kernel C: combine NBLK partials, normalize, h = W_j_w @ u_norm + W_j_b,
// out = h>0 ? h : expm1(h). One block, 128 threads.
// ---------------------------------------------------------------------------
__global__ void finalize_kernel(const float* __restrict__ W_j_w,
                                const float* __restrict__ W_j_b,
                                float* __restrict__ out) {
    __shared__ float sf[NBLK];
    __shared__ float sred[F];
    __shared__ float sun[F];
    const int t = threadIdx.x;  // 128 threads

    // global max
    float lm = -1e30f;
    for (int b = t; b < NBLK; b += F) lm = fmaxf(lm, g_m[b]);
    sred[t] = lm;
    __syncthreads();
    for (int off = 64; off > 0; off >>= 1) {
        if (t < off) sred[t] = fmaxf(sred[t], sred[t + off]);
        __syncthreads();
    }
    const float mg = sred[0];
    __syncthreads();

    // per-block scale factors + global sum
    float ls = 0.f;
    for (int b = t; b < NBLK; b += F) {
        const float f = __expf(g_m[b] - mg);
        sf[b] = f;
        ls += f * g_s[b];
    }
    sred[t] = ls;
    __syncthreads();
    for (int off = 64; off > 0; off >>= 1) {
        if (t < off) sred[t] += sred[t + off];
        __syncthreads();
    }
    const float S = sred[0];

    // combine u partials (coalesced: consecutive t -> consecutive addresses)
    float acc = 0.f;
    for (int b = 0; b < NBLK; b++) acc += sf[b] * g_u[b * F + t];
    sun[t] = acc / S;
    __syncthreads();

    // h = W_j_w @ u_norm + W_j_b
    float h = W_j_b[t];
#pragma unroll 4
    for (int k = 0; k < F; k++) h += W_j_w[t * F + k] * sun[k];

    out[t] = (h > 0.f) ? h : expm1f(h);
}

// ---------------------------------------------------------------------------
extern "C" void kernel_launch(void* const* d_in, const int* in_sizes, int n_in,
                              void* d_out, int out_size) {
    const float* h_i   = (const float*)d_in[0];
    const float* h_j   = (const float*)d_in[1];
    const float* W_i_w = (const float*)d_in[2];
    const float* W_i_b = (const float*)d_in[3];
    const float* W_j_w = (const float*)d_in[4];
    const float* W_j_b = (const float*)d_in[5];
    const float* W_ij  = (const float*)d_in[6];
    float* out = (float*)d_out;

    prep_kernel<<<1, 128>>>(h_i, W_i_w, W_i_b, W_j_w, W_j_b, W_ij);
    pass_kernel<<<NBLK, TPB>>>(h_j);
    finalize_kernel<<<1, 128>>>(W_j_w, W_j_b, out);
}

// round 3
// speedup vs baseline: 1.9294x; 1.9294x over previous
#include <cuda_runtime.h>
#include <math.h>

#define NJ    400000
#define F     128
#define NBLK  888            // 6 blocks/SM x 148 SMs, one wave; 888 = 8*111
#define TPB   256
#define WPB   (TPB / 32)
#define NW    (NBLK * WPB)   // total warps in pass

// Scratch (allocation-free rule: __device__ globals)
__device__ float g_v[F];
__device__ float g_c0;
__device__ float g_m[NBLK];
__device__ float g_s[NBLK];
__device__ float g_u[NBLK * F];

// ---------------------------------------------------------------------------
// Kernel A: precompute, parallelized on 1024 threads (32 warps).
//   z_i[f] = W_i_w[f,:]·h_i + W_i_b[f]       (warp-per-row, coalesced)
//   v[t]   = sum_f W_j_w[f,t] * w_r[f]        (8 f-slices x 128 t, coalesced)
//   c0     = sum_f w_l[f]*z_i[f] + W_j_b[f]*w_r[f]
// ---------------------------------------------------------------------------
__global__ void __launch_bounds__(1024) prep_kernel(
        const float* __restrict__ h_i,
        const float* __restrict__ W_i_w,
        const float* __restrict__ W_i_b,
        const float* __restrict__ W_j_w,
        const float* __restrict__ W_j_b,
        const float* __restrict__ W_ij) {
    __shared__ float s_hi[F];
    __shared__ float s_z[F];
    __shared__ float s_pv[8 * F];
    __shared__ float s_red[F];

    const int tid  = threadIdx.x;
    const int wid  = tid >> 5;
    const int lane = tid & 31;

    if (tid < F) s_hi[tid] = h_i[tid];
    __syncthreads();

    // z_i: warp wid handles rows wid, wid+32, wid+64, wid+96
    const float4* hi4 = reinterpret_cast<const float4*>(s_hi);
    const float4  hv  = hi4[lane];
#pragma unroll
    for (int r = 0; r < 4; r++) {
        const int f = wid + 32 * r;
        const float4 wrow = reinterpret_cast<const float4*>(W_i_w + f * F)[lane];
        float d = wrow.x * hv.x + wrow.y * hv.y + wrow.z * hv.z + wrow.w * hv.w;
        d += __shfl_xor_sync(0xffffffffu, d, 16);
        d += __shfl_xor_sync(0xffffffffu, d, 8);
        d += __shfl_xor_sync(0xffffffffu, d, 4);
        d += __shfl_xor_sync(0xffffffffu, d, 2);
        d += __shfl_xor_sync(0xffffffffu, d, 1);
        if (lane == 0) s_z[f] = d + W_i_b[f];
    }

    // v: slice s handles f in [s*16, s*16+16); t coalesced
    {
        const int slice = tid >> 7;          // 0..7
        const int t     = tid & 127;
        float acc = 0.f;
#pragma unroll
        for (int k = 0; k < 16; k++) {
            const int f = slice * 16 + k;
            acc += W_j_w[f * F + t] * W_ij[F + f];
        }
        s_pv[slice * F + t] = acc;
    }
    __syncthreads();

    if (tid < F) {
        float v = 0.f;
#pragma unroll
        for (int s = 0; s < 8; s++) v += s_pv[s * F + tid];
        g_v[tid] = v;
        s_red[tid] = W_ij[tid] * s_z[tid] + W_j_b[tid] * W_ij[F + tid];
    }
    __syncthreads();
    if (tid < 64) { s_red[tid] += s_red[tid + 64]; } __syncthreads();
    if (tid < 32) {
        float c = s_red[tid] + s_red[tid + 32];
        c += __shfl_xor_sync(0xffffffffu, c, 16);
        c += __shfl_xor_sync(0xffffffffu, c, 8);
        c += __shfl_xor_sync(0xffffffffu, c, 4);
        c += __shfl_xor_sync(0xffffffffu, c, 2);
        c += __shfl_xor_sync(0xffffffffu, c, 1);
        if (tid == 0) g_c0 = c;
    }
}

// ---------------------------------------------------------------------------
// Kernel B: single streaming pass over h_j with online softmax.
// One warp per PAIR of consecutive rows; lane l owns features [4l,4l+4).
// Two independent shuffle-reduction chains interleave; one state update
// amortized over 2 rows. Prefetch one pair ahead.
// NJ is even, so row < NJ implies row+1 < NJ (no intra-pair tail).
// ---------------------------------------------------------------------------
__global__ void __launch_bounds__(TPB) pass_kernel(const float* __restrict__ h_j) {
    __shared__ float sv[F];
    __shared__ float red_m[WPB];
    __shared__ float red_s[WPB];
    __shared__ float red_u[WPB * F];
    __shared__ float s_mb;

    for (int i = threadIdx.x; i < F; i += TPB) sv[i] = g_v[i];
    __syncthreads();

    const float c0   = g_c0;
    const int  warp  = threadIdx.x >> 5;
    const int  lane  = threadIdx.x & 31;
    const int  gw    = blockIdx.x * WPB + warp;
    const int  stride = NW * 2;

    const float4 vv = reinterpret_cast<const float4*>(sv)[lane];
    const float4* __restrict__ hj4 = reinterpret_cast<const float4*>(h_j);

    float m = -1e30f, ssum = 0.f;
    float ux = 0.f, uy = 0.f, uz = 0.f, uw = 0.f;

    int row = gw * 2;
    float4 x0 = make_float4(0.f, 0.f, 0.f, 0.f);
    float4 x1 = x0;
    if (row < NJ) {
        x0 = __ldg(hj4 + (size_t)row * 32 + lane);
        x1 = __ldg(hj4 + (size_t)row * 32 + 32 + lane);
    }

    while (row < NJ) {
        const int nrow = row + stride;
        float4 xn0 = x0, xn1 = x1;
        if (nrow < NJ) {
            xn0 = __ldg(hj4 + (size_t)nrow * 32 + lane);
            xn1 = __ldg(hj4 + (size_t)nrow * 32 + 32 + lane);
        }

        // Two independent dot reductions (ILP-interleaved by scheduler)
        float d0 = x0.x * vv.x + x0.y * vv.y + x0.z * vv.z + x0.w * vv.w;
        float d1 = x1.x * vv.x + x1.y * vv.y + x1.z * vv.z + x1.w * vv.w;
#pragma unroll
        for (int off = 16; off > 0; off >>= 1) {
            d0 += __shfl_xor_sync(0xffffffffu, d0, off);
            d1 += __shfl_xor_sync(0xffffffffu, d1, off);
        }

        const float s0 = d0 + c0;
        const float s1 = d1 + c0;
        const float e0 = (s0 > 0.f) ? s0 : 0.1f * s0;
        const float e1 = (s1 > 0.f) ? s1 : 0.1f * s1;

        // Online softmax update over both rows at once
        const float mn    = fmaxf(m, fmaxf(e0, e1));
        const float scale = __expf(m - mn);
        const float w0    = __expf(e0 - mn);
        const float w1    = __expf(e1 - mn);
        ssum = ssum * scale + w0 + w1;
        ux   = ux * scale + w0 * x0.x + w1 * x1.x;
        uy   = uy * scale + w0 * x0.y + w1 * x1.y;
        uz   = uz * scale + w0 * x0.z + w1 * x1.z;
        uw   = uw * scale + w0 * x0.w + w1 * x1.w;
        m = mn;

        x0 = xn0; x1 = xn1;
        row = nrow;
    }

    if (lane == 0) { red_m[warp] = m; red_s[warp] = ssum; }
    red_u[warp * F + lane * 4 + 0] = ux;
    red_u[warp * F + lane * 4 + 1] = uy;
    red_u[warp * F + lane * 4 + 2] = uz;
    red_u[warp * F + lane * 4 + 3] = uw;
    __syncthreads();

    if (threadIdx.x == 0) {
        float mb = red_m[0];
#pragma unroll
        for (int w2 = 1; w2 < WPB; w2++) mb = fmaxf(mb, red_m[w2]);
        s_mb = mb;
    }
    __syncthreads();
    const float mb = s_mb;

    const int t = threadIdx.x;
    if (t < F) {
        float acc = 0.f;
#pragma unroll
        for (int w2 = 0; w2 < WPB; w2++)
            acc += __expf(red_m[w2] - mb) * red_u[w2 * F + t];
        g_u[blockIdx.x * F + t] = acc;
    }
    if (t == 0) {
        float sb = 0.f;
#pragma unroll
        for (int w2 = 0; w2 < WPB; w2++) sb += __expf(red_m[w2] - mb) * red_s[w2];
        g_s[blockIdx.x] = sb;
        g_m[blockIdx.x] = mb;
    }
}

// ---------------------------------------------------------------------------
// Kernel C: combine NBLK partials, normalize, h = W_j_w @ u_norm + W_j_b,
// out = h>0 ? h : expm1(h). One block, 1024 threads (parallelized).
// ---------------------------------------------------------------------------
__global__ void __launch_bounds__(1024) finalize_kernel(
        const float* __restrict__ W_j_w,
        const float* __restrict__ W_j_b,
        float* __restrict__ out) {
    __shared__ float sf[NBLK];
    __shared__ float sred[1024];
    __shared__ float s_pu[8 * F];
    __shared__ float sun[F];
    __shared__ float s_mg, s_S;

    const int tid  = threadIdx.x;
    const int wid  = tid >> 5;
    const int lane = tid & 31;

    // ---- global max over NBLK block maxima ----
    float lm = (tid < NBLK) ? g_m[tid] : -1e30f;
    sred[tid] = lm;
    __syncthreads();
#pragma unroll
    for (int off = 512; off >= 32; off >>= 1) {
        if (tid < off) sred[tid] = fmaxf(sred[tid], sred[tid + off]);
        __syncthreads();
    }
    if (tid < 32) {
        float v = sred[tid];
#pragma unroll
        for (int off = 16; off > 0; off >>= 1)
            v = fmaxf(v, __shfl_xor_sync(0xffffffffu, v, off));
        if (tid == 0) s_mg = v;
    }
    __syncthreads();
    const float mg = s_mg;

    // ---- per-block scale factors + global sum ----
    float ls = 0.f;
    if (tid < NBLK) {
        const float fct = __expf(g_m[tid] - mg);
        sf[tid] = fct;
        ls = fct * g_s[tid];
    }
    sred[tid] = ls;
    __syncthreads();
#pragma unroll
    for (int off = 512; off >= 32; off >>= 1) {
        if (tid < off) sred[tid] += sred[tid + off];
        __syncthreads();
    }
    if (tid < 32) {
        float v = sred[tid];
#pragma unroll
        for (int off = 16; off > 0; off >>= 1)
            v += __shfl_xor_sync(0xffffffffu, v, off);
        if (tid == 0) s_S = v;
    }
    __syncthreads();
    const float S = s_S;

    // ---- combine u partials: 8 b-slices x 128 features (888 = 8*111) ----
    {
        const int slice = tid >> 7;   // 0..7
        const int t     = tid & 127;
        float acc = 0.f;
        const int b0 = slice * 111;
#pragma unroll 4
        for (int k = 0; k < 111; k++) {
            const int b = b0 + k;
            acc += sf[b] * g_u[b * F + t];
        }
        s_pu[slice * F + t] = acc;
    }
    __syncthreads();
    if (tid < F) {
        float acc = 0.f;
#pragma unroll
        for (int s = 0; s < 8; s++) acc += s_pu[s * F + tid];
        sun[tid] = acc / S;
    }
    __syncthreads();

    // ---- h = W_j_w @ u_norm + b : warp-per-row, coalesced ----
    const float4 uv = reinterpret_cast<const float4*>(sun)[lane];
#pragma unroll
    for (int r = 0; r < 4; r++) {
        const int f = wid + 32 * r;
        const float4 wrow = reinterpret_cast<const float4*>(W_j_w + f * F)[lane];
        float d = wrow.x * uv.x + wrow.y * uv.y + wrow.z * uv.z + wrow.w * uv.w;
        d += __shfl_xor_sync(0xffffffffu, d, 16);
        d += __shfl_xor_sync(0xffffffffu, d, 8);
        d += __shfl_xor_sync(0xffffffffu, d, 4);
        d += __shfl_xor_sync(0xffffffffu, d, 2);
        d += __shfl_xor_sync(0xffffffffu, d, 1);
        if (lane == 0) {
            const float h = d + W_j_b[f];
            out[f] = (h > 0.f) ? h : expm1f(h);
        }
    }
}

// ---------------------------------------------------------------------------
extern "C" void kernel_launch(void* const* d_in, const int* in_sizes, int n_in,
                              void* d_out, int out_size) {
    const float* h_i   = (const float*)d_in[0];
    const float* h_j   = (const float*)d_in[1];
    const float* W_i_w = (const float*)d_in[2];
    const float* W_i_b = (const float*)d_in[3];
    const float* W_j_w = (const float*)d_in[4];
    const float* W_j_b = (const float*)d_in[5];
    const float* W_ij  = (const float*)d_in[6];
    float* out = (float*)d_out;

    prep_kernel<<<1, 1024>>>(h_i, W_i_w, W_i_b, W_j_w, W_j_b, W_ij);
    pass_kernel<<<NBLK, TPB>>>(h_j);
    finalize_kernel<<<1, 1024>>>(W_j_w, W_j_b, out);
}